// round 4
// baseline (speedup 1.0000x reference)
#include <cuda_runtime.h>
#include <math.h>

#define L_DIM 16384
#define B_DIM 64
#define K_DIM 16
#define N_ROWS (B_DIM * K_DIM)     // 1024
#define MASK_BLOCKS B_DIM          // 64
#define TOTAL_BLOCKS (N_ROWS + MASK_BLOCKS)   // 1088
#define THREADS 256
#define ITERS (L_DIM / 4 / THREADS)           // 16
#define BATCH 8                                // loads in flight per thread
#define GROUPS (ITERS / BATCH)                 // 2
#define CAP 2048
#define THR_FIXED 2.0f            // speculative gather threshold (N(0,1) logits)

// Scratch (allocation-free rule: __device__ globals)
__device__ float g_nmask[B_DIM];
__device__ float g_sp2[N_ROWS];
__device__ float g_spm[N_ROWS];
__device__ unsigned int g_done = 0;

__global__ void __launch_bounds__(THREADS) fused_kernel(
    const float* __restrict__ logits,
    const float* __restrict__ mask,
    float* __restrict__ out)
{
    __shared__ float sval[CAP];
    __shared__ int   sidx[CAP];
    __shared__ int   s_cnt;
    __shared__ float s_red[THREADS / 32];
    __shared__ float s_max;
    __shared__ float s_fin[THREADS];
    __shared__ unsigned int s_ticket;

    const int blk  = blockIdx.x;
    const int tid  = threadIdx.x;
    const int warp = tid >> 5, lane = tid & 31;

    if (blk >= N_ROWS) {
        // ----------------- mask-sum block (one per batch) -----------------
        const int b = blk - N_ROWS;
        const float4* m4 = (const float4*)(mask + (size_t)b * L_DIM);
        float s = 0.f;
        #pragma unroll
        for (int g = 0; g < GROUPS; g++) {
            float4 v[BATCH];
            #pragma unroll
            for (int j = 0; j < BATCH; j++) v[j] = m4[tid + (g * BATCH + j) * THREADS];
            #pragma unroll
            for (int j = 0; j < BATCH; j++) s += (v[j].x + v[j].y) + (v[j].z + v[j].w);
        }
        #pragma unroll
        for (int o = 16; o; o >>= 1) s += __shfl_xor_sync(0xffffffffu, s, o);
        if (lane == 0) s_red[warp] = s;
        __syncthreads();
        if (tid == 0) {
            float t = 0.f;
            #pragma unroll
            for (int w = 0; w < THREADS / 32; w++) t += s_red[w];
            g_nmask[b] = t;
        }
    } else {
        // ----------------------- row block (b,k) ---------------------------
        const int row = blk;
        const float4* z4 = (const float4*)(logits + (size_t)row * L_DIM);
        if (tid == 0) s_cnt = 0;
        __syncthreads();

        // ---- single DRAM pass: max + speculative candidate gather ----
        float m = -3.4e38f;
        #pragma unroll
        for (int g = 0; g < GROUPS; g++) {
            float4 v[BATCH];
            #pragma unroll
            for (int j = 0; j < BATCH; j++) v[j] = z4[tid + (g * BATCH + j) * THREADS];
            #pragma unroll
            for (int j = 0; j < BATCH; j++) {
                float4 q = v[j];
                float vm = fmaxf(fmaxf(q.x, q.y), fmaxf(q.z, q.w));
                m = fmaxf(m, vm);
                if (vm > THR_FIXED) {   // rare (~2.5% of quads) — push candidates
                    int i = tid + (g * BATCH + j) * THREADS;
                    if (q.x > THR_FIXED) { int p = atomicAdd(&s_cnt, 1); if (p < CAP) { sval[p] = q.x; sidx[p] = 4 * i + 0; } }
                    if (q.y > THR_FIXED) { int p = atomicAdd(&s_cnt, 1); if (p < CAP) { sval[p] = q.y; sidx[p] = 4 * i + 1; } }
                    if (q.z > THR_FIXED) { int p = atomicAdd(&s_cnt, 1); if (p < CAP) { sval[p] = q.z; sidx[p] = 4 * i + 2; } }
                    if (q.w > THR_FIXED) { int p = atomicAdd(&s_cnt, 1); if (p < CAP) { sval[p] = q.w; sidx[p] = 4 * i + 3; } }
                }
            }
        }
        #pragma unroll
        for (int o = 16; o; o >>= 1) m = fmaxf(m, __shfl_xor_sync(0xffffffffu, m, o));
        if (lane == 0) s_red[warp] = m;
        __syncthreads();
        if (tid == 0) {
            float t = s_red[0];
            #pragma unroll
            for (int w = 1; w < THREADS / 32; w++) t = fmaxf(t, s_red[w]);
            s_max = t;
        }
        __syncthreads();
        const float supp_thr = s_max - 1.0f;   // support ⊆ {z > max-1}

        // ---- fallback (≈never): speculative set may miss support, re-gather from L2 ----
        if (supp_thr < THR_FIXED || s_cnt >= CAP) {
            __syncthreads();
            if (tid == 0) s_cnt = 0;
            __syncthreads();
            #pragma unroll
            for (int it = 0; it < ITERS; it++) {
                int i = tid + it * THREADS;
                float4 q = z4[i];
                if (q.x > supp_thr) { int p = atomicAdd(&s_cnt, 1); if (p < CAP) { sval[p] = q.x; sidx[p] = 4 * i + 0; } }
                if (q.y > supp_thr) { int p = atomicAdd(&s_cnt, 1); if (p < CAP) { sval[p] = q.y; sidx[p] = 4 * i + 1; } }
                if (q.z > supp_thr) { int p = atomicAdd(&s_cnt, 1); if (p < CAP) { sval[p] = q.z; sidx[p] = 4 * i + 2; } }
                if (q.w > supp_thr) { int p = atomicAdd(&s_cnt, 1); if (p < CAP) { sval[p] = q.w; sidx[p] = 4 * i + 3; } }
            }
            __syncthreads();
        }
        const int cnt = min(s_cnt, CAP);

        // ---- warp 0: Michelot iteration (start at tau = max-1), loss terms ----
        if (warp == 0) {
            float tau = supp_thr;   // tau* >= max-1; {z > max-1} superset of support, nonempty
            for (int iter = 0; iter < 64; iter++) {
                float s = 0.f; int c = 0;
                for (int i = lane; i < cnt; i += 32) {
                    float v = sval[i];
                    if (v > tau) { s += v; c++; }
                }
                #pragma unroll
                for (int o = 16; o; o >>= 1) {
                    s += __shfl_xor_sync(0xffffffffu, s, o);
                    c += __shfl_xor_sync(0xffffffffu, c, o);
                }
                float nt = (s - 1.0f) / (float)c;
                if (nt == tau) break;
                tau = nt;
            }

            const int b = row >> 4;
            const float* mrow = mask + (size_t)b * L_DIM;
            float sp2 = 0.f, spm = 0.f;
            for (int i = lane; i < cnt; i += 32) {
                float p = sval[i] - tau;
                if (p > 0.f) {
                    sp2 += p * p;
                    spm += mrow[sidx[i]] * p;   // mask is 0/1; inv_n applied at the end
                }
            }
            #pragma unroll
            for (int o = 16; o; o >>= 1) {
                sp2 += __shfl_xor_sync(0xffffffffu, sp2, o);
                spm += __shfl_xor_sync(0xffffffffu, spm, o);
            }
            if (lane == 0) {
                g_sp2[row] = sp2;
                g_spm[row] = spm;
            }
        }
    }

    // ------------- last-block-done final reduction (deterministic) ---------
    __syncthreads();
    __threadfence();
    if (tid == 0) s_ticket = atomicAdd(&g_done, 1u);
    __syncthreads();
    if (s_ticket == TOTAL_BLOCKS - 1) {
        float acc = 0.f;
        #pragma unroll
        for (int j = 0; j < N_ROWS / THREADS; j++) {
            int r = tid + j * THREADS;
            int b = r >> 4;
            float inv_n = 1.0f / fmaxf(g_nmask[b], 1e-12f);
            acc += 0.5f * g_sp2[r] - inv_n * g_spm[r] + 0.5f * inv_n;
        }
        s_fin[tid] = acc;
        __syncthreads();
        #pragma unroll
        for (int o = THREADS / 2; o > 0; o >>= 1) {
            if (tid < o) s_fin[tid] += s_fin[tid + o];
            __syncthreads();
        }
        if (tid == 0) {
            out[0] = s_fin[0] * (1.0f / (float)N_ROWS);
            g_done = 0;        // reset for next graph replay
        }
    }
}

// ---------------------------------------------------------------------------
extern "C" void kernel_launch(void* const* d_in, const int* in_sizes, int n_in,
                              void* d_out, int out_size) {
    const float* logits = (const float*)d_in[0];   // (64,16,16384) fp32
    const float* mask   = (const float*)d_in[1];   // (64,16384) fp32
    float* out = (float*)d_out;

    fused_kernel<<<TOTAL_BLOCKS, THREADS>>>(logits, mask, out);
}

// round 5
// speedup vs baseline: 1.3657x; 1.3657x over previous
#include <cuda_runtime.h>
#include <math.h>

#define L_DIM 16384
#define B_DIM 64
#define K_DIM 16
#define N_ROWS (B_DIM * K_DIM)     // 1024
#define MASK_BLOCKS B_DIM          // 64
#define TOTAL_BLOCKS (N_ROWS + MASK_BLOCKS)   // 1088
#define THREADS 256
#define ITERS (L_DIM / 4 / THREADS)           // 16 quads per thread
#define BATCH 8                                // loads in flight per thread
#define GROUPS (ITERS / BATCH)                 // 2
#define CAP 1024
#define THR_FIXED 2.0f            // speculative flag threshold (N(0,1) logits)

// Scratch (allocation-free rule: __device__ globals)
__device__ float g_nmask[B_DIM];
__device__ float g_sp2[N_ROWS];
__device__ float g_spm[N_ROWS];
__device__ unsigned int g_done = 0;

__global__ void __launch_bounds__(THREADS) fused_kernel(
    const float* __restrict__ logits,
    const float* __restrict__ mask,
    float* __restrict__ out)
{
    __shared__ float sval[CAP];
    __shared__ int   sidx[CAP];
    __shared__ int   s_cnt;
    __shared__ float s_red[THREADS / 32];
    __shared__ float s_max;
    __shared__ float s_fin[THREADS];
    __shared__ unsigned int s_ticket;

    const int blk  = blockIdx.x;
    const int tid  = threadIdx.x;
    const int warp = tid >> 5, lane = tid & 31;

    if (blk >= N_ROWS) {
        // ----------------- mask-sum block (one per batch) -----------------
        const int b = blk - N_ROWS;
        const float4* m4 = (const float4*)(mask + (size_t)b * L_DIM);
        float s = 0.f;
        #pragma unroll
        for (int g = 0; g < GROUPS; g++) {
            float4 v[BATCH];
            #pragma unroll
            for (int j = 0; j < BATCH; j++) v[j] = m4[tid + (g * BATCH + j) * THREADS];
            #pragma unroll
            for (int j = 0; j < BATCH; j++) s += (v[j].x + v[j].y) + (v[j].z + v[j].w);
        }
        #pragma unroll
        for (int o = 16; o; o >>= 1) s += __shfl_xor_sync(0xffffffffu, s, o);
        if (lane == 0) s_red[warp] = s;
        __syncthreads();
        if (tid == 0) {
            float t = 0.f;
            #pragma unroll
            for (int w = 0; w < THREADS / 32; w++) t += s_red[w];
            g_nmask[b] = t;
        }
    } else {
        // ----------------------- row block (b,k) ---------------------------
        const int row = blk;
        const float4* z4 = (const float4*)(logits + (size_t)row * L_DIM);
        if (tid == 0) s_cnt = 0;
        __syncthreads();

        // ---- pass 1: branch-free DRAM pass: max + per-quad flag bits ----
        float m = -3.4e38f;
        unsigned int qmask = 0u;
        #pragma unroll
        for (int g = 0; g < GROUPS; g++) {
            float4 v[BATCH];
            #pragma unroll
            for (int j = 0; j < BATCH; j++) v[j] = z4[tid + (g * BATCH + j) * THREADS];
            #pragma unroll
            for (int j = 0; j < BATCH; j++) {
                float vm = fmaxf(fmaxf(v[j].x, v[j].y), fmaxf(v[j].z, v[j].w));
                m = fmaxf(m, vm);
                qmask |= (vm > THR_FIXED ? 1u : 0u) << (g * BATCH + j);
            }
        }
        #pragma unroll
        for (int o = 16; o; o >>= 1) m = fmaxf(m, __shfl_xor_sync(0xffffffffu, m, o));
        if (lane == 0) s_red[warp] = m;
        __syncthreads();
        if (tid == 0) {
            float t = s_red[0];
            #pragma unroll
            for (int w = 1; w < THREADS / 32; w++) t = fmaxf(t, s_red[w]);
            s_max = t;
        }
        __syncthreads();
        const float supp_thr = s_max - 1.0f;   // support ⊆ {z > max-1}

        if (supp_thr >= THR_FIXED) {
            // ---- pass 2 (fast path): revisit only flagged quads (~0.4/thread, L1/L2 hot) ----
            unsigned int qm = qmask;
            while (qm) {
                int j = __ffs(qm) - 1;
                qm &= qm - 1u;
                int i = tid + j * THREADS;
                float4 q = z4[i];
                if (q.x > supp_thr) { int p = atomicAdd(&s_cnt, 1); if (p < CAP) { sval[p] = q.x; sidx[p] = 4 * i + 0; } }
                if (q.y > supp_thr) { int p = atomicAdd(&s_cnt, 1); if (p < CAP) { sval[p] = q.y; sidx[p] = 4 * i + 1; } }
                if (q.z > supp_thr) { int p = atomicAdd(&s_cnt, 1); if (p < CAP) { sval[p] = q.z; sidx[p] = 4 * i + 2; } }
                if (q.w > supp_thr) { int p = atomicAdd(&s_cnt, 1); if (p < CAP) { sval[p] = q.w; sidx[p] = 4 * i + 3; } }
            }
            __syncthreads();
        }
        if (supp_thr < THR_FIXED || s_cnt >= CAP) {
            // ---- fallback (≈never): full re-gather from L2 at supp_thr ----
            __syncthreads();
            if (tid == 0) s_cnt = 0;
            __syncthreads();
            #pragma unroll
            for (int it = 0; it < ITERS; it++) {
                int i = tid + it * THREADS;
                float4 q = z4[i];
                if (q.x > supp_thr) { int p = atomicAdd(&s_cnt, 1); if (p < CAP) { sval[p] = q.x; sidx[p] = 4 * i + 0; } }
                if (q.y > supp_thr) { int p = atomicAdd(&s_cnt, 1); if (p < CAP) { sval[p] = q.y; sidx[p] = 4 * i + 1; } }
                if (q.z > supp_thr) { int p = atomicAdd(&s_cnt, 1); if (p < CAP) { sval[p] = q.z; sidx[p] = 4 * i + 2; } }
                if (q.w > supp_thr) { int p = atomicAdd(&s_cnt, 1); if (p < CAP) { sval[p] = q.w; sidx[p] = 4 * i + 3; } }
            }
            __syncthreads();
        }
        const int cnt = min(s_cnt, CAP);

        // ---- warp 0: Michelot iteration (start at tau = max-1), loss terms ----
        if (warp == 0) {
            float tau = supp_thr;   // tau* >= max-1; candidate set ⊇ support, nonempty
            for (int iter = 0; iter < 64; iter++) {
                float s = 0.f; int c = 0;
                for (int i = lane; i < cnt; i += 32) {
                    float v = sval[i];
                    if (v > tau) { s += v; c++; }
                }
                #pragma unroll
                for (int o = 16; o; o >>= 1) {
                    s += __shfl_xor_sync(0xffffffffu, s, o);
                    c += __shfl_xor_sync(0xffffffffu, c, o);
                }
                float nt = (s - 1.0f) / (float)c;
                if (nt == tau) break;
                tau = nt;
            }

            const int b = row >> 4;
            const float* mrow = mask + (size_t)b * L_DIM;
            float sp2 = 0.f, spm = 0.f;
            for (int i = lane; i < cnt; i += 32) {
                float p = sval[i] - tau;
                if (p > 0.f) {
                    sp2 += p * p;
                    spm += mrow[sidx[i]] * p;   // mask is 0/1; inv_n applied at the end
                }
            }
            #pragma unroll
            for (int o = 16; o; o >>= 1) {
                sp2 += __shfl_xor_sync(0xffffffffu, sp2, o);
                spm += __shfl_xor_sync(0xffffffffu, spm, o);
            }
            if (lane == 0) {
                g_sp2[row] = sp2;
                g_spm[row] = spm;
            }
        }
    }

    // ------------- last-block-done final reduction (deterministic) ---------
    __syncthreads();
    __threadfence();
    if (tid == 0) s_ticket = atomicAdd(&g_done, 1u);
    __syncthreads();
    if (s_ticket == TOTAL_BLOCKS - 1) {
        float acc = 0.f;
        #pragma unroll
        for (int j = 0; j < N_ROWS / THREADS; j++) {
            int r = tid + j * THREADS;
            int b = r >> 4;
            float inv_n = 1.0f / fmaxf(g_nmask[b], 1e-12f);
            acc += 0.5f * g_sp2[r] - inv_n * g_spm[r] + 0.5f * inv_n;
        }
        s_fin[tid] = acc;
        __syncthreads();
        #pragma unroll
        for (int o = THREADS / 2; o > 0; o >>= 1) {
            if (tid < o) s_fin[tid] += s_fin[tid + o];
            __syncthreads();
        }
        if (tid == 0) {
            out[0] = s_fin[0] * (1.0f / (float)N_ROWS);
            g_done = 0;        // reset for next graph replay
        }
    }
}

// ---------------------------------------------------------------------------
extern "C" void kernel_launch(void* const* d_in, const int* in_sizes, int n_in,
                              void* d_out, int out_size) {
    const float* logits = (const float*)d_in[0];   // (64,16,16384) fp32
    const float* mask   = (const float*)d_in[1];   // (64,16384) fp32
    float* out = (float*)d_out;

    fused_kernel<<<TOTAL_BLOCKS, THREADS>>>(logits, mask, out);
}

// round 6
// speedup vs baseline: 1.4265x; 1.0445x over previous
#include <cuda_runtime.h>
#include <math.h>

#define L_DIM 16384
#define B_DIM 64
#define K_DIM 16
#define N_ROWS (B_DIM * K_DIM)     // 1024
#define MASK_BLOCKS B_DIM          // 64
#define TOTAL_BLOCKS (N_ROWS + MASK_BLOCKS)   // 1088
#define THREADS 512
#define ITERS (L_DIM / 4 / THREADS)           // 8 quads per thread == one batch
#define CAP 1024
#define THR_FIXED 2.0f            // speculative flag threshold (N(0,1) logits)

// Scratch (allocation-free rule: __device__ globals)
__device__ float g_nmask[B_DIM];
__device__ float g_sp2[N_ROWS];
__device__ float g_spm[N_ROWS];
__device__ unsigned int g_done = 0;

__global__ void __launch_bounds__(THREADS, 2) fused_kernel(
    const float* __restrict__ logits,
    const float* __restrict__ mask,
    float* __restrict__ out)
{
    __shared__ float sval[CAP];
    __shared__ int   sidx[CAP];
    __shared__ int   s_cnt;
    __shared__ float s_red[THREADS / 32];
    __shared__ float s_max;
    __shared__ float s_fin[THREADS];
    __shared__ unsigned int s_ticket;

    const int blk  = blockIdx.x;
    const int tid  = threadIdx.x;
    const int warp = tid >> 5, lane = tid & 31;

    if (blk >= N_ROWS) {
        // ----------------- mask-sum block (one per batch) -----------------
        const int b = blk - N_ROWS;
        const float4* m4 = (const float4*)(mask + (size_t)b * L_DIM);
        float4 v[ITERS];
        #pragma unroll
        for (int j = 0; j < ITERS; j++) v[j] = m4[tid + j * THREADS];
        float s = 0.f;
        #pragma unroll
        for (int j = 0; j < ITERS; j++) s += (v[j].x + v[j].y) + (v[j].z + v[j].w);
        #pragma unroll
        for (int o = 16; o; o >>= 1) s += __shfl_xor_sync(0xffffffffu, s, o);
        if (lane == 0) s_red[warp] = s;
        __syncthreads();
        if (tid == 0) {
            float t = 0.f;
            #pragma unroll
            for (int w = 0; w < THREADS / 32; w++) t += s_red[w];
            g_nmask[b] = t;
        }
    } else {
        // ----------------------- row block (b,k) ---------------------------
        const int row = blk;
        const float4* z4 = (const float4*)(logits + (size_t)row * L_DIM);
        if (tid == 0) s_cnt = 0;

        // ---- pass 1: one front-batched burst of 8 LDG.128 covers the row ----
        float4 v[ITERS];
        #pragma unroll
        for (int j = 0; j < ITERS; j++) v[j] = z4[tid + j * THREADS];

        float m = -3.4e38f;
        unsigned int qmask = 0u;
        #pragma unroll
        for (int j = 0; j < ITERS; j++) {
            float vm = fmaxf(fmaxf(v[j].x, v[j].y), fmaxf(v[j].z, v[j].w));
            m = fmaxf(m, vm);
            qmask |= (vm > THR_FIXED ? 1u : 0u) << j;
        }
        #pragma unroll
        for (int o = 16; o; o >>= 1) m = fmaxf(m, __shfl_xor_sync(0xffffffffu, m, o));
        if (lane == 0) s_red[warp] = m;
        __syncthreads();
        if (tid == 0) {
            float t = s_red[0];
            #pragma unroll
            for (int w = 1; w < THREADS / 32; w++) t = fmaxf(t, s_red[w]);
            s_max = t;
        }
        __syncthreads();
        const float supp_thr = s_max - 1.0f;   // support ⊆ {z > max-1}

        if (supp_thr >= THR_FIXED) {
            // ---- pass 2 (fast path): only flagged quads, values still in regs ----
            unsigned int qm = qmask;
            while (qm) {
                int j = __ffs(qm) - 1;
                qm &= qm - 1u;
                int i = tid + j * THREADS;
                float4 q = z4[i];   // L1-hot reload (cheaper than keeping v[] live)
                if (q.x > supp_thr) { int p = atomicAdd(&s_cnt, 1); if (p < CAP) { sval[p] = q.x; sidx[p] = 4 * i + 0; } }
                if (q.y > supp_thr) { int p = atomicAdd(&s_cnt, 1); if (p < CAP) { sval[p] = q.y; sidx[p] = 4 * i + 1; } }
                if (q.z > supp_thr) { int p = atomicAdd(&s_cnt, 1); if (p < CAP) { sval[p] = q.z; sidx[p] = 4 * i + 2; } }
                if (q.w > supp_thr) { int p = atomicAdd(&s_cnt, 1); if (p < CAP) { sval[p] = q.w; sidx[p] = 4 * i + 3; } }
            }
            __syncthreads();
        }
        if (supp_thr < THR_FIXED || s_cnt >= CAP) {
            // ---- fallback (≈never): full re-gather from L2 at supp_thr ----
            __syncthreads();
            if (tid == 0) s_cnt = 0;
            __syncthreads();
            #pragma unroll
            for (int it = 0; it < ITERS; it++) {
                int i = tid + it * THREADS;
                float4 q = z4[i];
                if (q.x > supp_thr) { int p = atomicAdd(&s_cnt, 1); if (p < CAP) { sval[p] = q.x; sidx[p] = 4 * i + 0; } }
                if (q.y > supp_thr) { int p = atomicAdd(&s_cnt, 1); if (p < CAP) { sval[p] = q.y; sidx[p] = 4 * i + 1; } }
                if (q.z > supp_thr) { int p = atomicAdd(&s_cnt, 1); if (p < CAP) { sval[p] = q.z; sidx[p] = 4 * i + 2; } }
                if (q.w > supp_thr) { int p = atomicAdd(&s_cnt, 1); if (p < CAP) { sval[p] = q.w; sidx[p] = 4 * i + 3; } }
            }
            __syncthreads();
        }
        const int cnt = min(s_cnt, CAP);

        // ---- warp 0: Michelot iteration (start at tau = max-1), loss terms ----
        if (warp == 0) {
            float tau = supp_thr;   // tau* >= max-1; candidate set ⊇ support, nonempty
            for (int iter = 0; iter < 64; iter++) {
                float s = 0.f; int c = 0;
                for (int i = lane; i < cnt; i += 32) {
                    float vv = sval[i];
                    if (vv > tau) { s += vv; c++; }
                }
                #pragma unroll
                for (int o = 16; o; o >>= 1) {
                    s += __shfl_xor_sync(0xffffffffu, s, o);
                    c += __shfl_xor_sync(0xffffffffu, c, o);
                }
                float nt = (s - 1.0f) / (float)c;
                if (nt == tau) break;
                tau = nt;
            }

            const int b = row >> 4;
            const float* mrow = mask + (size_t)b * L_DIM;
            float sp2 = 0.f, spm = 0.f;
            for (int i = lane; i < cnt; i += 32) {
                float p = sval[i] - tau;
                if (p > 0.f) {
                    sp2 += p * p;
                    spm += mrow[sidx[i]] * p;   // mask is 0/1; inv_n applied at the end
                }
            }
            #pragma unroll
            for (int o = 16; o; o >>= 1) {
                sp2 += __shfl_xor_sync(0xffffffffu, sp2, o);
                spm += __shfl_xor_sync(0xffffffffu, spm, o);
            }
            if (lane == 0) {
                g_sp2[row] = sp2;
                g_spm[row] = spm;
            }
        }
    }

    // ------------- last-block-done final reduction (deterministic) ---------
    __syncthreads();
    __threadfence();
    if (tid == 0) s_ticket = atomicAdd(&g_done, 1u);
    __syncthreads();
    if (s_ticket == TOTAL_BLOCKS - 1) {
        float acc = 0.f;
        #pragma unroll
        for (int j = 0; j < N_ROWS / THREADS; j++) {
            int r = tid + j * THREADS;
            int b = r >> 4;
            float inv_n = 1.0f / fmaxf(g_nmask[b], 1e-12f);
            acc += 0.5f * g_sp2[r] - inv_n * g_spm[r] + 0.5f * inv_n;
        }
        s_fin[tid] = acc;
        __syncthreads();
        #pragma unroll
        for (int o = THREADS / 2; o > 0; o >>= 1) {
            if (tid < o) s_fin[tid] += s_fin[tid + o];
            __syncthreads();
        }
        if (tid == 0) {
            out[0] = s_fin[0] * (1.0f / (float)N_ROWS);
            g_done = 0;        // reset for next graph replay
        }
    }
}

// ---------------------------------------------------------------------------
extern "C" void kernel_launch(void* const* d_in, const int* in_sizes, int n_in,
                              void* d_out, int out_size) {
    const float* logits = (const float*)d_in[0];   // (64,16,16384) fp32
    const float* mask   = (const float*)d_in[1];   // (64,16384) fp32
    float* out = (float*)d_out;

    fused_kernel<<<TOTAL_BLOCKS, THREADS>>>(logits, mask, out);
}